// round 1
// baseline (speedup 1.0000x reference)
#include <cuda_runtime.h>

#define BATCH 16
#define CH    256
#define IH    100
#define IW    100
#define NBOX  100
#define RH    40
#define RW    40
#define NCLS  599

// Scratch (no allocations allowed): pooled box features + quantized boxes + validity
__device__ float         g_pooled[BATCH * CH * NBOX];   // [B][C][N]
__device__ int           g_box[BATCH * NBOX * 4];       // x1,y1,x2,y2 (post-clip)
__device__ unsigned char g_valid[BATCH * NBOX];

// ---------------------------------------------------------------------------
// Kernel 0: quantize boxes to the 40x40 grid (round half-to-even like jnp.round)
// ---------------------------------------------------------------------------
__global__ void box_kernel(const float* __restrict__ boxes) {
    int i = blockIdx.x * blockDim.x + threadIdx.x;
    if (i >= BATCH * NBOX) return;
    const float s = 40.0f / 1024.0f;  // exact in fp32
    float b0 = rintf(boxes[i * 4 + 0] * s);
    float b1 = rintf(boxes[i * 4 + 1] * s);
    float b2 = rintf(boxes[i * 4 + 2] * s);
    float b3 = rintf(boxes[i * 4 + 3] * s);
    int x1 = max((int)b0, 0);
    int y1 = max((int)b1, 0);
    int x2 = min((int)b2, RW);
    int y2 = min((int)b3, RH);
    bool v = (x1 < x2) && (y1 < y2);
    // safe clip (mirrors reference's clip for the integral-image indices)
    x1 = min(max(x1, 0), RW);  x2 = min(max(x2, 0), RW);
    y1 = min(max(y1, 0), RH);  y2 = min(max(y2, 0), RH);
    g_box[i * 4 + 0] = x1;  g_box[i * 4 + 1] = y1;
    g_box[i * 4 + 2] = x2;  g_box[i * 4 + 3] = y2;
    g_valid[i] = v ? 1 : 0;
}

// ---------------------------------------------------------------------------
// Kernel 1: per (b,c) plane — bilinear 100->40 resize, 41x41 integral image,
// then exact box-average pooling for all 100 boxes. All in shared memory.
// ---------------------------------------------------------------------------
__global__ __launch_bounds__(256) void resize_pool_kernel(const float* __restrict__ feat) {
    __shared__ float res[RH * RW];              // 6.4 KB
    __shared__ float ii[(RH + 1) * (RW + 1)];   // 6.7 KB

    const int bc  = blockIdx.x;        // b*CH + c
    const int b   = bc / CH;
    const int tid = threadIdx.x;
    const float* __restrict__ in = feat + (size_t)bc * (IH * IW);

    // --- bilinear resize (half-pixel centers): src = 2.5*dst + 0.75 ---
    #pragma unroll
    for (int i = tid; i < RH * RW; i += 256) {
        int oy = i / RW, ox = i % RW;
        float sy = 2.5f * (float)oy + 0.75f;   // exact; frac is 0.75 or 0.25
        float sx = 2.5f * (float)ox + 0.75f;
        int y0 = (int)sy;  float fy = sy - (float)y0;
        int x0 = (int)sx;  float fx = sx - (float)x0;
        const float* p = in + y0 * IW + x0;
        float v00 = __ldg(p);
        float v01 = __ldg(p + 1);
        float v10 = __ldg(p + IW);
        float v11 = __ldg(p + IW + 1);
        float top = (1.0f - fx) * v00 + fx * v01;
        float bot = (1.0f - fx) * v10 + fx * v11;
        res[i] = (1.0f - fy) * top + fy * bot;
    }
    __syncthreads();

    // --- integral image: row prefix sums (rows 1..40); zero top row ---
    if (tid < RH) {
        float run = 0.0f;
        int base = (tid + 1) * (RW + 1);
        ii[base] = 0.0f;
        #pragma unroll 8
        for (int x = 0; x < RW; x++) {
            run += res[tid * RW + x];
            ii[base + x + 1] = run;
        }
    } else if (tid >= 64 && tid < 64 + (RW + 1)) {
        ii[tid - 64] = 0.0f;               // ii[0][*] = 0
    }
    __syncthreads();

    // --- column prefix sums (in place, down each of 41 columns) ---
    if (tid < RW + 1) {
        float run = 0.0f;
        #pragma unroll 8
        for (int y = 1; y <= RH; y++) {
            run += ii[y * (RW + 1) + tid];
            ii[y * (RW + 1) + tid] = run;
        }
    }
    __syncthreads();

    // --- pooled value for each box (threads 0..99), coalesced write [B][C][N] ---
    if (tid < NBOX) {
        int gi = b * NBOX + tid;
        float out = 0.0f;
        if (g_valid[gi]) {
            int x1 = g_box[gi * 4 + 0], y1 = g_box[gi * 4 + 1];
            int x2 = g_box[gi * 4 + 2], y2 = g_box[gi * 4 + 3];
            float s = ii[y2 * (RW + 1) + x2] - ii[y1 * (RW + 1) + x2]
                    - ii[y2 * (RW + 1) + x1] + ii[y1 * (RW + 1) + x1];
            float area = (float)((y2 - y1) * (x2 - x1));
            out = s / area;
        }
        g_pooled[(size_t)bc * NBOX + tid] = out;
    }
}

// ---------------------------------------------------------------------------
// Kernel 2: scatter-mean per (b, class). One CTA per (class, b); thread = channel.
// Condition (class match + valid) is uniform across threads -> no divergence.
// ---------------------------------------------------------------------------
__global__ __launch_bounds__(CH) void class_mean_kernel(const int* __restrict__ gt,
                                                        float* __restrict__ out) {
    __shared__ int           s_cls[NBOX];
    __shared__ unsigned char s_val[NBOX];
    const int cls = blockIdx.x;   // 0..598
    const int b   = blockIdx.y;   // 0..15
    const int tid = threadIdx.x;  // channel

    if (tid < NBOX) {
        s_cls[tid] = gt[b * NBOX + tid];
        s_val[tid] = g_valid[b * NBOX + tid];
    }
    __syncthreads();

    float sum = 0.0f;
    int   cnt = 0;
    const float* __restrict__ pool = g_pooled + ((size_t)b * CH + tid) * NBOX;
    #pragma unroll 4
    for (int n = 0; n < NBOX; n++) {
        if (s_cls[n] == cls && s_val[n]) {   // uniform across warp
            sum += pool[n];
            cnt++;
        }
    }
    out[((size_t)b * NCLS + cls) * CH + tid] = (cnt > 0) ? (sum / (float)cnt) : 0.0f;
}

// ---------------------------------------------------------------------------
extern "C" void kernel_launch(void* const* d_in, const int* in_sizes, int n_in,
                              void* d_out, int out_size) {
    const float* feat  = (const float*)d_in[0];   // [16,256,100,100] f32
    const float* boxes = (const float*)d_in[1];   // [16,100,4] f32
    const int*   gt    = (const int*)d_in[2];     // [16,100] i32
    float* out = (float*)d_out;                   // [16,599,256] f32

    box_kernel<<<(BATCH * NBOX + 255) / 256, 256>>>(boxes);
    resize_pool_kernel<<<BATCH * CH, 256>>>(feat);
    dim3 g2(NCLS, BATCH);
    class_mean_kernel<<<g2, CH>>>(gt, out);
}

// round 2
// speedup vs baseline: 1.4671x; 1.4671x over previous
#include <cuda_runtime.h>

#define BATCH 16
#define CH    256
#define IH    100
#define IW    100
#define NBOX  100
#define RH    40
#define RW    40
#define NCLS  599
#define CPB   2          // channels per CTA in resize/pool kernel

// Scratch: pooled box features [B][C][N]
__device__ float g_pooled[BATCH * CH * NBOX];

// Quantize one box (xyxy, image coords) to the 40x40 grid. Matches
// jnp.round (half-to-even) + clip semantics of the reference.
__device__ __forceinline__ int quantize_box(float4 bb, bool& valid) {
    const float s = 40.0f / 1024.0f;          // exact in fp32
    int x1 = max((int)rintf(bb.x * s), 0);
    int y1 = max((int)rintf(bb.y * s), 0);
    int x2 = min((int)rintf(bb.z * s), RW);
    int y2 = min((int)rintf(bb.w * s), RH);
    valid = (x1 < x2) && (y1 < y2);
    x1 = min(max(x1, 0), RW);  x2 = min(max(x2, 0), RW);
    y1 = min(max(y1, 0), RH);  y2 = min(max(y2, 0), RH);
    return x1 | (y1 << 8) | (x2 << 16) | (y2 << 24);
}

// ---------------------------------------------------------------------------
// Kernel 1: per (b, c..c+1) planes — bilinear 100->40 resize into smem, then
// direct box-sum pooling (boxes are <=5x5 cells on the 40x40 grid).
// ---------------------------------------------------------------------------
__global__ __launch_bounds__(256) void resize_pool_kernel(
        const float* __restrict__ feat, const float* __restrict__ boxes) {
    __shared__ float res[CPB][RH * RW];       // 2 x 6.4 KB
    __shared__ int   s_box[NBOX];             // packed x1,y1,x2,y2

    const int blk  = blockIdx.x;              // 0 .. BATCH*CH/CPB-1
    const int b    = blk / (CH / CPB);
    const int cbas = (blk % (CH / CPB)) * CPB;
    const int tid  = threadIdx.x;

    // --- quantize this batch's boxes (threads 0..99) ---
    if (tid < NBOX) {
        float4 bb = __ldg((const float4*)boxes + b * NBOX + tid);
        bool v;
        int pk = quantize_box(bb, v);
        s_box[tid] = v ? pk : 0;              // invalid -> x1==x2==0
    }

    // --- bilinear resize (half-pixel centers): src = 2.5*dst + 0.75 ---
    const float* __restrict__ in0 = feat + (size_t)(b * CH + cbas) * (IH * IW);
    const float* __restrict__ in1 = in0 + IH * IW;
    for (int i = tid; i < RH * RW; i += 256) {
        int oy = i / RW, ox = i % RW;
        float sy = 2.5f * (float)oy + 0.75f;  // frac is exactly .75 or .25
        float sx = 2.5f * (float)ox + 0.75f;
        int y0 = (int)sy;  float fy = sy - (float)y0;
        int x0 = (int)sx;  float fx = sx - (float)x0;
        int off = y0 * IW + x0;
        float a00 = __ldg(in0 + off),      a01 = __ldg(in0 + off + 1);
        float a10 = __ldg(in0 + off + IW), a11 = __ldg(in0 + off + IW + 1);
        float b00 = __ldg(in1 + off),      b01 = __ldg(in1 + off + 1);
        float b10 = __ldg(in1 + off + IW), b11 = __ldg(in1 + off + IW + 1);
        float gx0 = 1.0f - fx, gy0 = 1.0f - fy;
        res[0][i] = gy0 * (gx0 * a00 + fx * a01) + fy * (gx0 * a10 + fx * a11);
        res[1][i] = gy0 * (gx0 * b00 + fx * b01) + fy * (gx0 * b10 + fx * b11);
    }
    __syncthreads();

    // --- direct box-average pooling: thread = (plane, box) ---
    if (tid < NBOX * CPB) {
        int n = tid % NBOX;
        int p = tid / NBOX;
        int pk = s_box[n];
        int x1 = pk & 0xFF, y1 = (pk >> 8) & 0xFF;
        int x2 = (pk >> 16) & 0xFF, y2 = (pk >> 24) & 0xFF;
        float out = 0.0f;
        if (x1 < x2) {                        // valid (invalid stored as 0)
            float s = 0.0f;
            const float* r = res[p];
            for (int y = y1; y < y2; y++) {
                float rs = 0.0f;
                for (int x = x1; x < x2; x++) rs += r[y * RW + x];
                s += rs;
            }
            out = s / (float)((y2 - y1) * (x2 - x1));
        }
        g_pooled[(size_t)(b * CH + cbas + p) * NBOX + n] = out;
    }
}

// ---------------------------------------------------------------------------
// Kernel 2: scatter-mean per (b, class). One CTA per (class, b); thread = channel.
// Most (b,cls) pairs have no matching box -> early zero write via syncthreads_count.
// ---------------------------------------------------------------------------
__global__ __launch_bounds__(CH) void class_mean_kernel(
        const float* __restrict__ boxes, const int* __restrict__ gt,
        float* __restrict__ out) {
    __shared__ unsigned char s_m[NBOX];
    const int cls = blockIdx.x;   // 0..598
    const int b   = blockIdx.y;   // 0..15
    const int tid = threadIdx.x;  // channel

    bool m = false;
    if (tid < NBOX) {
        float4 bb = __ldg((const float4*)boxes + b * NBOX + tid);
        bool v;
        (void)quantize_box(bb, v);
        m = v && (__ldg(gt + b * NBOX + tid) == cls);
        s_m[tid] = m ? 1 : 0;
    }
    int cnt = __syncthreads_count(m);

    float r = 0.0f;
    if (cnt > 0) {
        const float* __restrict__ pool = g_pooled + (size_t)(b * CH + tid) * NBOX;
        float sum = 0.0f;
        #pragma unroll 4
        for (int n = 0; n < NBOX; n++)
            if (s_m[n]) sum += __ldg(pool + n);   // uniform predicate across warp
        r = sum / (float)cnt;
    }
    out[(size_t)(b * NCLS + cls) * CH + tid] = r;
}

// ---------------------------------------------------------------------------
extern "C" void kernel_launch(void* const* d_in, const int* in_sizes, int n_in,
                              void* d_out, int out_size) {
    const float* feat  = (const float*)d_in[0];   // [16,256,100,100] f32
    const float* boxes = (const float*)d_in[1];   // [16,100,4] f32
    const int*   gt    = (const int*)d_in[2];     // [16,100] i32
    float* out = (float*)d_out;                   // [16,599,256] f32

    resize_pool_kernel<<<BATCH * CH / CPB, 256>>>(feat, boxes);
    dim3 g2(NCLS, BATCH);
    class_mean_kernel<<<g2, CH>>>(boxes, gt, out);
}